// round 15
// baseline (speedup 1.0000x reference)
#include <cuda_runtime.h>
#include <cuda_fp16.h>
#include <cstdint>
#include <math.h>

#define S_LEN 2048
#define BATCH 2
#define HID   2048
#define NH    16
#define NKV   4
#define HD    128
#define MROWS (BATCH*S_LEN)   // 4096

// ---------------- scratch (static device globals; no runtime alloc) -------
__device__ float g_q[(size_t)MROWS * (NH*HD)];
__device__ float g_k[(size_t)MROWS * (NKV*HD)];
__device__ __half g_hh[(size_t)MROWS * HID];        // hidden fp16
__device__ __half g_qh[(size_t)MROWS * (NH*HD)];    // Q post-rope fp16
__device__ __half g_kh[(size_t)MROWS * (NKV*HD)];   // K post-rope fp16
__device__ __half g_vh[(size_t)MROWS * (NKV*HD)];   // V fp16
__device__ __half g_oh[(size_t)MROWS * (NH*HD)];    // attn out fp16
// fp16 transposed weights [N][K]
__device__ __half g_wqh[(size_t)HID * HID];
__device__ __half g_wkh[(size_t)(NKV*HD) * HID];
__device__ __half g_wvh[(size_t)(NKV*HD) * HID];
__device__ __half g_woh[(size_t)HID * HID];

// ======================= PTX helpers ======================================
__device__ __forceinline__ uint32_t smem_u32(const void* p) {
    uint32_t a;
    asm("{ .reg .u64 t; cvta.to.shared.u64 t, %1; cvt.u32.u64 %0, t; }"
        : "=r"(a) : "l"(p));
    return a;
}
__device__ __forceinline__ void ldsm4(uint32_t* r, uint32_t addr) {
    asm volatile("ldmatrix.sync.aligned.m8n8.x4.shared.b16 {%0,%1,%2,%3}, [%4];"
        : "=r"(r[0]), "=r"(r[1]), "=r"(r[2]), "=r"(r[3]) : "r"(addr));
}
__device__ __forceinline__ void ldsm4t(uint32_t* r, uint32_t addr) {
    asm volatile("ldmatrix.sync.aligned.m8n8.x4.trans.shared.b16 {%0,%1,%2,%3}, [%4];"
        : "=r"(r[0]), "=r"(r[1]), "=r"(r[2]), "=r"(r[3]) : "r"(addr));
}
__device__ __forceinline__ void mma_f16(float* c, const uint32_t* a,
                                        uint32_t b0, uint32_t b1) {
    asm volatile(
        "mma.sync.aligned.m16n8k16.row.col.f32.f16.f16.f32 "
        "{%0,%1,%2,%3}, {%4,%5,%6,%7}, {%8,%9}, {%0,%1,%2,%3};"
        : "+f"(c[0]), "+f"(c[1]), "+f"(c[2]), "+f"(c[3])
        : "r"(a[0]), "r"(a[1]), "r"(a[2]), "r"(a[3]), "r"(b0), "r"(b1));
}
__device__ __forceinline__ float ex2f(float x) {
    float y; asm("ex2.approx.f32 %0, %1;" : "=f"(y) : "f"(x)); return y;
}
__device__ __forceinline__ void cp16(uint32_t dst, const void* src) {
    asm volatile("cp.async.ca.shared.global [%0], [%1], 16;" :: "r"(dst), "l"(src));
}
#define CP_COMMIT() asm volatile("cp.async.commit_group;" ::: "memory")
#define CP_WAIT(N)  asm volatile("cp.async.wait_group %0;" :: "n"(N) : "memory")

__device__ __forceinline__ uint32_t packh2(float a, float b) {
    __half2 t = __floats2half2_rn(a, b);
    return *(uint32_t*)&t;
}

// ======================= fused prep: weights transpose + hidden convert ===
#define WQ_BLKS ((HID/32) * (HID/32))          // 4096
#define WK_BLKS ((HID/32) * ((NKV*HD)/32))     // 1024
#define WV_BLKS WK_BLKS                        // 1024
#define WO_BLKS WQ_BLKS                        // 4096
#define WALL_BLKS (WQ_BLKS + WK_BLKS + WV_BLKS + WO_BLKS)  // 10240
#define HCONV_BLKS ((MROWS * HID) / (256 * 4)) // 8192
#define PREP_BLKS (WALL_BLKS + HCONV_BLKS)     // 18432

__global__ void prep_all(const float* __restrict__ wq, const float* __restrict__ wk,
                         const float* __restrict__ wv, const float* __restrict__ wo,
                         const float* __restrict__ hid,
                         __half* __restrict__ dq, __half* __restrict__ dk,
                         __half* __restrict__ dv, __half* __restrict__ dwo,
                         __half* __restrict__ dh)
{
    const int bid = blockIdx.x;
    const int tid = threadIdx.x;
    if (bid >= WALL_BLKS) {
        const size_t i4 = ((size_t)(bid - WALL_BLKS) * 256 + tid) * 4;
        float4 v = *(const float4*)(hid + i4);
        __half2 lo = __floats2half2_rn(v.x, v.y);
        __half2 hi = __floats2half2_rn(v.z, v.w);
        *(uint32_t*)(dh + i4)     = *(uint32_t*)&lo;
        *(uint32_t*)(dh + i4 + 2) = *(uint32_t*)&hi;
        return;
    }
    __shared__ float tile[32][33];
    const float* src; __half* dst; int N, lb;
    if (bid < WQ_BLKS) {
        src = wq; dst = dq;  N = HID;    lb = bid;
    } else if (bid < WQ_BLKS + WK_BLKS) {
        src = wk; dst = dk;  N = NKV*HD; lb = bid - WQ_BLKS;
    } else if (bid < WQ_BLKS + WK_BLKS + WV_BLKS) {
        src = wv; dst = dv;  N = NKV*HD; lb = bid - WQ_BLKS - WK_BLKS;
    } else {
        src = wo; dst = dwo; N = HID;    lb = bid - WQ_BLKS - WK_BLKS - WV_BLKS;
    }
    const int kb = HID / 32;
    const int k0 = (lb % kb) * 32;
    const int n0 = (lb / kb) * 32;
    const int x = tid & 31;
    const int y0 = tid >> 5;
#pragma unroll
    for (int y = y0; y < 32; y += 8)
        tile[y][x] = src[(size_t)(k0 + y) * N + n0 + x];
    __syncthreads();
#pragma unroll
    for (int y = y0; y < 32; y += 8)
        dst[(size_t)(n0 + y) * HID + k0 + x] = __float2half_rn(tile[x][y]);
}

// ======================= RoPE: 1 trig per (bs,i), applied to all heads ====
__global__ void rope_both(const float* __restrict__ Qf, const float* __restrict__ Kf,
                          const float* __restrict__ tvals, const float* __restrict__ rope_w,
                          __half* __restrict__ Qh, __half* __restrict__ Kh)
{
    const int idx = blockIdx.x * blockDim.x + threadIdx.x;
    if (idx >= MROWS * 64) return;
    const int i  = idx & 63;
    const int bs = idx >> 6;

    const float t = tvals[bs];
    const float inv_f = expf(-(float)(2 * i) * (9.210340371976184f / 128.0f));
    const float fr = t * inv_f * rope_w[i];
    const float cs = cosf(fr);
    const float sn = sinf(fr);

    const float* qrow = Qf + (size_t)bs * (NH * HD);
    __half* qo = Qh + (size_t)bs * (NH * HD);
#pragma unroll
    for (int h = 0; h < NH; h++) {
        const float x1 = qrow[h * HD + i];
        const float x2 = qrow[h * HD + i + 64];
        qo[h * HD + i]      = __float2half_rn(x1 * cs - x2 * sn);
        qo[h * HD + i + 64] = __float2half_rn(x2 * cs + x1 * sn);
    }
    const float* krow = Kf + (size_t)bs * (NKV * HD);
    __half* ko = Kh + (size_t)bs * (NKV * HD);
#pragma unroll
    for (int h = 0; h < NKV; h++) {
        const float x1 = krow[h * HD + i];
        const float x2 = krow[h * HD + i + 64];
        ko[h * HD + i]      = __float2half_rn(x1 * cs - x2 * sn);
        ko[h * HD + i + 64] = __float2half_rn(x2 * cs + x1 * sn);
    }
}

// ======================= GEMM common ======================================
#define GK   HID
#define CHK  32
#define NCHK (GK / CHK)        // 64
#define GPAD 40
#define GT_H (128 * GPAD)
#define NSTG 3
#define QSTG_B (2 * GT_H * 2)  // A + B per stage (20480 B)
#define GRID_PERS 444

// ---------- merged QKV GEMM: grid-stride over 24x32 tiles -----------------
#define QKV_TILES (24 * (MROWS/128))   // 768

__global__ __launch_bounds__(256) void qkv_gemm(
    const __half* __restrict__ Ah16,
    const __half* __restrict__ wq16, const __half* __restrict__ wk16,
    const __half* __restrict__ wv16,
    const float* __restrict__ bq, const float* __restrict__ bk,
    const float* __restrict__ bv,
    float* __restrict__ Qo, float* __restrict__ Ko, __half* __restrict__ Vo)
{
    extern __shared__ __half sg[];
    const uint32_t sbase = smem_u32(sg);

    const int tid  = threadIdx.x;
    const int lane = tid & 31;
    const int wid  = tid >> 5;
    const int wm   = wid & 3;
    const int wn   = wid >> 2;

    for (int tile = blockIdx.x; tile < QKV_TILES; tile += GRID_PERS) {
        const int nx = tile % 24;
        const int bm = (tile / 24) * 128;

        const __half* WT; const float* bias;
        float* outF = nullptr; __half* outH = nullptr;
        int N, bn;
        if (nx < 16)      { WT = wq16; bias = bq; outF = Qo; N = NH*HD;  bn = nx * 128; }
        else if (nx < 20) { WT = wk16; bias = bk; outF = Ko; N = NKV*HD; bn = (nx-16) * 128; }
        else              { WT = wv16; bias = bv; outH = Vo; N = NKV*HD; bn = (nx-20) * 128; }

        float c[2][8][4];
#pragma unroll
        for (int mi = 0; mi < 2; mi++)
#pragma unroll
            for (int ni = 0; ni < 8; ni++)
#pragma unroll
                for (int j = 0; j < 4; j++) c[mi][ni][j] = 0.f;

        auto issue = [&](int kt, int stg) {
            const uint32_t sb = sbase + stg * QSTG_B;
#pragma unroll
            for (int j = 0; j < 2; j++) {
                const int cch = tid * 2 + j;
                const int row = cch >> 2;
                const int off = (cch & 3) * 8;
                const uint32_t d = sb + (row * GPAD + off) * 2;
                cp16(d,            Ah16 + (size_t)(bm + row) * GK + kt * CHK + off);
                cp16(d + GT_H * 2, WT   + (size_t)(bn + row) * GK + kt * CHK + off);
            }
            CP_COMMIT();
        };

        issue(0, 0);
        issue(1, 1);

        for (int kt = 0; kt < NCHK; kt++) {
            CP_WAIT(1);
            __syncthreads();

            const uint32_t stage = sbase + (kt % NSTG) * QSTG_B;
            const uint32_t Ahs = stage;
            const uint32_t Bhs = Ahs + GT_H * 2;

#pragma unroll
            for (int ks = 0; ks < 2; ks++) {
                const int k0 = ks * 16;
                uint32_t ah[8];
#pragma unroll
                for (int mi = 0; mi < 2; mi++) {
                    const uint32_t aoff =
                        ((wm * 32 + mi * 16 + (lane & 7) + ((lane >> 3) & 1) * 8) * GPAD
                         + k0 + (lane >> 4) * 8) * 2;
                    ldsm4(ah + 4 * mi, Ahs + aoff);
                }
#pragma unroll
                for (int bg = 0; bg < 4; bg++) {
                    const uint32_t boff =
                        ((wn * 64 + bg * 16 + (lane & 7) + (lane >> 4) * 8) * GPAD
                         + k0 + ((lane >> 3) & 1) * 8) * 2;
                    uint32_t bh[4];
                    ldsm4(bh, Bhs + boff);
#pragma unroll
                    for (int tt = 0; tt < 2; tt++) {
                        const int ni = bg * 2 + tt;
                        mma_f16(c[0][ni], ah,     bh[2*tt], bh[2*tt+1]);
                        mma_f16(c[1][ni], ah + 4, bh[2*tt], bh[2*tt+1]);
                    }
                }
            }
            __syncthreads();
            if (kt + 2 < NCHK) issue(kt + 2, (kt + 2) % NSTG);
            else CP_COMMIT();
        }

#pragma unroll
        for (int mi = 0; mi < 2; mi++) {
            const int row0 = bm + wm * 32 + mi * 16 + (lane >> 2);
#pragma unroll
            for (int ni = 0; ni < 8; ni++) {
                const int col = bn + wn * 64 + ni * 8 + (lane & 3) * 2;
                const float b0 = __ldg(bias + col);
                const float b1 = __ldg(bias + col + 1);
                const float y00 = c[mi][ni][0] + b0, y01 = c[mi][ni][1] + b1;
                const float y10 = c[mi][ni][2] + b0, y11 = c[mi][ni][3] + b1;
                if (outH) {
                    *(uint32_t*)(outH + (size_t)row0 * N + col)       = packh2(y00, y01);
                    *(uint32_t*)(outH + (size_t)(row0 + 8) * N + col) = packh2(y10, y11);
                } else {
                    float2 r0, r1;
                    r0.x = y00; r0.y = y01;
                    r1.x = y10; r1.y = y11;
                    *(float2*)(outF + (size_t)row0 * N + col)       = r0;
                    *(float2*)(outF + (size_t)(row0 + 8) * N + col) = r1;
                }
            }
        }
    }
}

// ---------- WO GEMM: grid-stride over 16x32 tiles -------------------------
#define WO_TILES ((HID/128) * (MROWS/128))   // 512

__global__ __launch_bounds__(256) void wo_gemm(
    const __half* __restrict__ Agh, const __half* __restrict__ WTh,
    float* __restrict__ C, int N)
{
    extern __shared__ __half sg[];
    const uint32_t sbase = smem_u32(sg);

    const int tid  = threadIdx.x;
    const int lane = tid & 31;
    const int wid  = tid >> 5;
    const int wm   = wid & 3;
    const int wn   = wid >> 2;

    for (int tile = blockIdx.x; tile < WO_TILES; tile += GRID_PERS) {
        const int bn = (tile % (HID/128)) * 128;
        const int bm = (tile / (HID/128)) * 128;

        float c[2][8][4];
#pragma unroll
        for (int mi = 0; mi < 2; mi++)
#pragma unroll
            for (int ni = 0; ni < 8; ni++)
#pragma unroll
                for (int j = 0; j < 4; j++) c[mi][ni][j] = 0.f;

        auto issue = [&](int kt, int stg) {
            const uint32_t sb = sbase + stg * QSTG_B;
#pragma unroll
            for (int j = 0; j < 2; j++) {
                const int cch = tid * 2 + j;
                const int row = cch >> 2;
                const int off = (cch & 3) * 8;
                const uint32_t d = sb + (row * GPAD + off) * 2;
                cp16(d,            Agh + (size_t)(bm + row) * GK + kt * CHK + off);
                cp16(d + GT_H * 2, WTh + (size_t)(bn + row) * GK + kt * CHK + off);
            }
            CP_COMMIT();
        };

        issue(0, 0);
        issue(1, 1);

        for (int kt = 0; kt < NCHK; kt++) {
            CP_WAIT(1);
            __syncthreads();

            const uint32_t stage = sbase + (kt % NSTG) * QSTG_B;
            const uint32_t Ahs = stage;
            const uint32_t Bhs = Ahs + GT_H * 2;

#pragma unroll
            for (int ks = 0; ks < 2; ks++) {
                const int k0 = ks * 16;
                uint32_t ah[8];
#pragma unroll
                for (int mi = 0; mi < 2; mi++) {
                    const uint32_t aoff =
                        ((wm * 32 + mi * 16 + (lane & 7) + ((lane >> 3) & 1) * 8) * GPAD
                         + k0 + (lane >> 4) * 8) * 2;
                    ldsm4(ah + 4 * mi, Ahs + aoff);
                }
#pragma unroll
                for (int bg = 0; bg < 4; bg++) {
                    const uint32_t boff =
                        ((wn * 64 + bg * 16 + (lane & 7) + (lane >> 4) * 8) * GPAD
                         + k0 + ((lane >> 3) & 1) * 8) * 2;
                    uint32_t bh[4];
                    ldsm4(bh, Bhs + boff);
#pragma unroll
                    for (int tt = 0; tt < 2; tt++) {
                        const int ni = bg * 2 + tt;
                        mma_f16(c[0][ni], ah,     bh[2*tt], bh[2*tt+1]);
                        mma_f16(c[1][ni], ah + 4, bh[2*tt], bh[2*tt+1]);
                    }
                }
            }
            __syncthreads();
            if (kt + 2 < NCHK) issue(kt + 2, (kt + 2) % NSTG);
            else CP_COMMIT();
        }

#pragma unroll
        for (int mi = 0; mi < 2; mi++) {
            const int row0 = bm + wm * 32 + mi * 16 + (lane >> 2);
#pragma unroll
            for (int ni = 0; ni < 8; ni++) {
                const int col = bn + wn * 64 + ni * 8 + (lane & 3) * 2;
                float2 r0, r1;
                r0.x = c[mi][ni][0]; r0.y = c[mi][ni][1];
                r1.x = c[mi][ni][2]; r1.y = c[mi][ni][3];
                *(float2*)(C + (size_t)row0 * N + col)       = r0;
                *(float2*)(C + (size_t)(row0 + 8) * N + col) = r1;
            }
        }
    }
}

// ======================= Flash attention (64-row CTA, 4 warps) ============
#define FPAD 136
#define FQT_H (64 * FPAD)            // q tile halves (64 rows)
#define FKT_H (64 * FPAD)            // kv tile halves

__global__ __launch_bounds__(128) void flash_mma(
    const __half* __restrict__ Qg, const __half* __restrict__ Kg,
    const __half* __restrict__ Vg, __half* __restrict__ Oh)
{
    extern __shared__ __half sf[];
    const uint32_t uQ = smem_u32(sf);
    const uint32_t uK = uQ + FQT_H * 2;
    const uint32_t uV = uK + FKT_H * 2;

    const int qb = gridDim.x - 1 - blockIdx.x;   // heavy CTAs first
    const int bh = blockIdx.y;
    const int b  = bh >> 4;
    const int h  = bh & 15;
    const int kvh = h >> 2;
    const int tid = threadIdx.x;
    const int lane = tid & 31;
    const int w = tid >> 5;               // 0..3 -> q rows w*16..w*16+15
    const int q0 = qb * 64;
    const int rowbase = b * S_LEN;

    // Q tile: 64 rows x 128 halves -> 1024 chunks / 128 thr = 8 each
    {
#pragma unroll
        for (int j = 0; j < 8; j++) {
            const int cch = tid * 8 + j;
            const int row = cch >> 4;
            const int off = (cch & 15) * 8;
            const size_t g = (size_t)(rowbase + q0 + row) * (NH * HD) + h * HD + off;
            cp16(uQ + (row * FPAD + off) * 2, Qg + g);
        }
    }
    auto issueKV = [&](int nb) {
#pragma unroll
        for (int j = 0; j < 8; j++) {
            const int cch = tid * 8 + j;
            const int row = cch >> 4;
            const int off = (cch & 15) * 8;
            const size_t g = (size_t)(rowbase + nb * 64 + row) * (NKV * HD) + kvh * HD + off;
            const uint32_t d = (row * FPAD + off) * 2;
            cp16(uK + d, Kg + g);
            cp16(uV + d, Vg + g);
        }
        CP_COMMIT();
    };
    issueKV(0);

    float o[16][4];
#pragma unroll
    for (int ni = 0; ni < 16; ni++)
#pragma unroll
        for (int j = 0; j < 4; j++) o[ni][j] = 0.f;
    float m0 = -1.0e30f, m1 = -1.0e30f, l0 = 0.f, l1 = 0.f;

    const float SC2 = 0.12751744900459843f;  // (1/sqrt(128)) * log2(e)
    const int nblocks = qb + 1;
    const int wrow0 = q0 + w * 16;

    for (int nb = 0; nb < nblocks; nb++) {
        const int n0 = nb * 64;
        CP_WAIT(0);
        __syncthreads();

        if (n0 <= wrow0 + 15) {
            float s[8][4];
#pragma unroll
            for (int ni = 0; ni < 8; ni++)
#pragma unroll
                for (int j = 0; j < 4; j++) s[ni][j] = 0.f;

#pragma unroll
            for (int ks = 0; ks < 8; ks++) {
                const int k0 = ks * 16;
                uint32_t a4[4];
                const uint32_t aoff =
                    ((w * 16 + (lane & 7) + ((lane >> 3) & 1) * 8) * FPAD
                     + k0 + (lane >> 4) * 8) * 2;
                ldsm4(a4, uQ + aoff);
#pragma unroll
                for (int bg = 0; bg < 4; bg++) {
                    const uint32_t boff =
                        ((bg * 16 + (lane & 7) + (lane >> 4) * 8) * FPAD
                         + k0 + ((lane >> 3) & 1) * 8) * 2;
                    uint32_t b4[4];
                    ldsm4(b4, uK + boff);
                    mma_f16(s[bg * 2],     a4, b4[0], b4[1]);
                    mma_f16(s[bg * 2 + 1], a4, b4[2], b4[3]);
                }
            }

            const int r0g = wrow0 + (lane >> 2);
            const int r1g = r0g + 8;
            const bool diag = (n0 + 63 > wrow0);
            float rmax0 = -1.0e30f, rmax1 = -1.0e30f;
#pragma unroll
            for (int ni = 0; ni < 8; ni++) {
                const int colb = n0 + ni * 8 + (lane & 3) * 2;
#pragma unroll
                for (int j = 0; j < 4; j++) {
                    float z = s[ni][j] * SC2;
                    if (diag) {
                        const int col = colb + (j & 1);
                        const int rw  = (j < 2) ? r0g : r1g;
                        if (col > rw) z = -1.0e30f;
                    }
                    s[ni][j] = z;
                }
                rmax0 = fmaxf(rmax0, fmaxf(s[ni][0], s[ni][1]));
                rmax1 = fmaxf(rmax1, fmaxf(s[ni][2], s[ni][3]));
            }
            rmax0 = fmaxf(rmax0, __shfl_xor_sync(0xffffffffu, rmax0, 1));
            rmax0 = fmaxf(rmax0, __shfl_xor_sync(0xffffffffu, rmax0, 2));
            rmax1 = fmaxf(rmax1, __shfl_xor_sync(0xffffffffu, rmax1, 1));
            rmax1 = fmaxf(rmax1, __shfl_xor_sync(0xffffffffu, rmax1, 2));

            const float mn0 = fmaxf(m0, rmax0);
            const float mn1 = fmaxf(m1, rmax1);
            const float al0 = ex2f(m0 - mn0);
            const float al1 = ex2f(m1 - mn1);
            m0 = mn0; m1 = mn1;

            float ls0 = 0.f, ls1 = 0.f;
#pragma unroll
            for (int ni = 0; ni < 8; ni++) {
                s[ni][0] = ex2f(s[ni][0] - mn0);
                s[ni][1] = ex2f(s[ni][1] - mn0);
                s[ni][2] = ex2f(s[ni][2] - mn1);
                s[ni][3] = ex2f(s[ni][3] - mn1);
                ls0 += s[ni][0] + s[ni][1];
                ls1 += s[ni][2] + s[ni][3];
            }
            l0 = l0 * al0 + ls0;
            l1 = l1 * al1 + ls1;
#pragma unroll
            for (int ni = 0; ni < 16; ni++) {
                o[ni][0] *= al0; o[ni][1] *= al0;
                o[ni][2] *= al1; o[ni][3] *= al1;
            }

#pragma unroll
            for (int kk = 0; kk < 4; kk++) {
                uint32_t ph[4];
                ph[0] = packh2(s[2*kk][0],   s[2*kk][1]);
                ph[1] = packh2(s[2*kk][2],   s[2*kk][3]);
                ph[2] = packh2(s[2*kk+1][0], s[2*kk+1][1]);
                ph[3] = packh2(s[2*kk+1][2], s[2*kk+1][3]);
#pragma unroll
                for (int vg = 0; vg < 8; vg++) {
                    const uint32_t voff =
                        ((kk * 16 + (lane & 7) + ((lane >> 3) & 1) * 8) * FPAD
                         + vg * 16 + (lane >> 4) * 8) * 2;
                    uint32_t v4[4];
                    ldsm4t(v4, uV + voff);
                    mma_f16(o[vg * 2],     ph, v4[0], v4[1]);
                    mma_f16(o[vg * 2 + 1], ph, v4[2], v4[3]);
                }
            }
        }

        __syncthreads();
        if (nb + 1 < nblocks) issueKV(nb + 1);
    }

    float lf0 = l0, lf1 = l1;
    lf0 += __shfl_xor_sync(0xffffffffu, lf0, 1);
    lf0 += __shfl_xor_sync(0xffffffffu, lf0, 2);
    lf1 += __shfl_xor_sync(0xffffffffu, lf1, 1);
    lf1 += __shfl_xor_sync(0xffffffffu, lf1, 2);
    const float inv0 = 1.f / lf0;
    const float inv1 = 1.f / lf1;

    const int gr0 = rowbase + wrow0 + (lane >> 2);
    const int gr1 = gr0 + 8;
#pragma unroll
    for (int ni = 0; ni < 16; ni++) {
        const int col = h * HD + ni * 8 + (lane & 3) * 2;
        *(uint32_t*)(Oh + (size_t)gr0 * (NH * HD) + col) =
            packh2(o[ni][0] * inv0, o[ni][1] * inv0);
        *(uint32_t*)(Oh + (size_t)gr1 * (NH * HD) + col) =
            packh2(o[ni][2] * inv1, o[ni][3] * inv1);
    }
}

// ======================= launch ===========================================
extern "C" void kernel_launch(void* const* d_in, const int* in_sizes, int n_in,
                              void* d_out, int out_size)
{
    const float* hidden = (const float*)d_in[0];
    const float* tvals  = (const float*)d_in[1];
    const float* wq     = (const float*)d_in[2];
    const float* bq     = (const float*)d_in[3];
    const float* wk     = (const float*)d_in[4];
    const float* bk     = (const float*)d_in[5];
    const float* wv     = (const float*)d_in[6];
    const float* bv     = (const float*)d_in[7];
    const float* wo     = (const float*)d_in[8];
    const float* rope_w = (const float*)d_in[9];
    float* out = (float*)d_out;

    float *q, *k;
    __half *hh, *qh, *kh, *vh, *oh, *wqh, *wkh, *wvh, *woh;
    cudaGetSymbolAddress((void**)&q,   g_q);
    cudaGetSymbolAddress((void**)&k,   g_k);
    cudaGetSymbolAddress((void**)&hh,  g_hh);
    cudaGetSymbolAddress((void**)&qh,  g_qh);
    cudaGetSymbolAddress((void**)&kh,  g_kh);
    cudaGetSymbolAddress((void**)&vh,  g_vh);
    cudaGetSymbolAddress((void**)&oh,  g_oh);
    cudaGetSymbolAddress((void**)&wqh, g_wqh);
    cudaGetSymbolAddress((void**)&wkh, g_wkh);
    cudaGetSymbolAddress((void**)&wvh, g_wvh);
    cudaGetSymbolAddress((void**)&woh, g_woh);

    // ---- prep ----
    prep_all<<<PREP_BLKS, 256>>>(wq, wk, wv, wo, hidden, wqh, wkh, wvh, woh, hh);

    // ---- merged QKV projection (grid-stride persistent) ----
    {
        const int qdyn = NSTG * QSTG_B;  // 61440
        cudaFuncSetAttribute(qkv_gemm, cudaFuncAttributeMaxDynamicSharedMemorySize, qdyn);
        qkv_gemm<<<GRID_PERS, 256, qdyn>>>(
            hh, wqh, wkh, wvh, bq, bk, bv, q, k, vh);
    }

    // ---- RoPE ----
    {
        int tot = MROWS * 64;
        rope_both<<<(tot + 255) / 256, 256>>>(q, k, tvals, rope_w, qh, kh);
    }

    // ---- Flash attention: 64-row CTAs, 4 warps, 3 CTAs/SM ----
    {
        const int fdyn = 3 * FKT_H * 2;  // Q + K + V = 52224 B
        cudaFuncSetAttribute(flash_mma, cudaFuncAttributeMaxDynamicSharedMemorySize, fdyn);
        flash_mma<<<dim3(S_LEN/64, BATCH*NH), 128, fdyn>>>(qh, kh, vh, oh);
    }

    // ---- Output projection (grid-stride persistent) ----
    {
        const int wdyn = NSTG * QSTG_B;
        cudaFuncSetAttribute(wo_gemm, cudaFuncAttributeMaxDynamicSharedMemorySize, wdyn);
        wo_gemm<<<GRID_PERS, 256, wdyn>>>(oh, woh, out, HID);
    }
}

// round 16
// speedup vs baseline: 1.1177x; 1.1177x over previous
#include <cuda_runtime.h>
#include <cuda_fp16.h>
#include <cstdint>
#include <math.h>

#define S_LEN 2048
#define BATCH 2
#define HID   2048
#define NH    16
#define NKV   4
#define HD    128
#define MROWS (BATCH*S_LEN)   // 4096

// ---------------- scratch (static device globals; no runtime alloc) -------
__device__ float g_q[(size_t)MROWS * (NH*HD)];
__device__ float g_k[(size_t)MROWS * (NKV*HD)];
__device__ __half g_hh[(size_t)MROWS * HID];        // hidden fp16
__device__ __half g_qh[(size_t)MROWS * (NH*HD)];    // Q post-rope fp16
__device__ __half g_kh[(size_t)MROWS * (NKV*HD)];   // K post-rope fp16
__device__ __half g_vh[(size_t)MROWS * (NKV*HD)];   // V fp16
__device__ __half g_oh[(size_t)MROWS * (NH*HD)];    // attn out fp16
// fp16 transposed weights [N][K]
__device__ __half g_wqh[(size_t)HID * HID];
__device__ __half g_wkh[(size_t)(NKV*HD) * HID];
__device__ __half g_wvh[(size_t)(NKV*HD) * HID];
__device__ __half g_woh[(size_t)HID * HID];

// ======================= PTX helpers ======================================
__device__ __forceinline__ uint32_t smem_u32(const void* p) {
    uint32_t a;
    asm("{ .reg .u64 t; cvta.to.shared.u64 t, %1; cvt.u32.u64 %0, t; }"
        : "=r"(a) : "l"(p));
    return a;
}
__device__ __forceinline__ void ldsm4(uint32_t* r, uint32_t addr) {
    asm volatile("ldmatrix.sync.aligned.m8n8.x4.shared.b16 {%0,%1,%2,%3}, [%4];"
        : "=r"(r[0]), "=r"(r[1]), "=r"(r[2]), "=r"(r[3]) : "r"(addr));
}
__device__ __forceinline__ void ldsm4t(uint32_t* r, uint32_t addr) {
    asm volatile("ldmatrix.sync.aligned.m8n8.x4.trans.shared.b16 {%0,%1,%2,%3}, [%4];"
        : "=r"(r[0]), "=r"(r[1]), "=r"(r[2]), "=r"(r[3]) : "r"(addr));
}
__device__ __forceinline__ void mma_f16(float* c, const uint32_t* a,
                                        uint32_t b0, uint32_t b1) {
    asm volatile(
        "mma.sync.aligned.m16n8k16.row.col.f32.f16.f16.f32 "
        "{%0,%1,%2,%3}, {%4,%5,%6,%7}, {%8,%9}, {%0,%1,%2,%3};"
        : "+f"(c[0]), "+f"(c[1]), "+f"(c[2]), "+f"(c[3])
        : "r"(a[0]), "r"(a[1]), "r"(a[2]), "r"(a[3]), "r"(b0), "r"(b1));
}
__device__ __forceinline__ float ex2f(float x) {
    float y; asm("ex2.approx.f32 %0, %1;" : "=f"(y) : "f"(x)); return y;
}
__device__ __forceinline__ void cp16(uint32_t dst, const void* src) {
    asm volatile("cp.async.ca.shared.global [%0], [%1], 16;" :: "r"(dst), "l"(src));
}
#define CP_COMMIT() asm volatile("cp.async.commit_group;" ::: "memory")
#define CP_WAIT(N)  asm volatile("cp.async.wait_group %0;" :: "n"(N) : "memory")

__device__ __forceinline__ uint32_t packh2(float a, float b) {
    __half2 t = __floats2half2_rn(a, b);
    return *(uint32_t*)&t;
}

// ======================= fused prep: weights transpose + hidden convert ===
#define WQ_BLKS ((HID/32) * (HID/32))          // 4096
#define WK_BLKS ((HID/32) * ((NKV*HD)/32))     // 1024
#define WV_BLKS WK_BLKS                        // 1024
#define WO_BLKS WQ_BLKS                        // 4096
#define WALL_BLKS (WQ_BLKS + WK_BLKS + WV_BLKS + WO_BLKS)  // 10240
#define HCONV_BLKS ((MROWS * HID) / (256 * 4)) // 8192
#define PREP_BLKS (WALL_BLKS + HCONV_BLKS)     // 18432

__global__ void prep_all(const float* __restrict__ wq, const float* __restrict__ wk,
                         const float* __restrict__ wv, const float* __restrict__ wo,
                         const float* __restrict__ hid,
                         __half* __restrict__ dq, __half* __restrict__ dk,
                         __half* __restrict__ dv, __half* __restrict__ dwo,
                         __half* __restrict__ dh)
{
    const int bid = blockIdx.x;
    const int tid = threadIdx.x;
    if (bid >= WALL_BLKS) {
        const size_t i4 = ((size_t)(bid - WALL_BLKS) * 256 + tid) * 4;
        float4 v = *(const float4*)(hid + i4);
        __half2 lo = __floats2half2_rn(v.x, v.y);
        __half2 hi = __floats2half2_rn(v.z, v.w);
        *(uint32_t*)(dh + i4)     = *(uint32_t*)&lo;
        *(uint32_t*)(dh + i4 + 2) = *(uint32_t*)&hi;
        return;
    }
    __shared__ float tile[32][33];
    const float* src; __half* dst; int N, lb;
    if (bid < WQ_BLKS) {
        src = wq; dst = dq;  N = HID;    lb = bid;
    } else if (bid < WQ_BLKS + WK_BLKS) {
        src = wk; dst = dk;  N = NKV*HD; lb = bid - WQ_BLKS;
    } else if (bid < WQ_BLKS + WK_BLKS + WV_BLKS) {
        src = wv; dst = dv;  N = NKV*HD; lb = bid - WQ_BLKS - WK_BLKS;
    } else {
        src = wo; dst = dwo; N = HID;    lb = bid - WQ_BLKS - WK_BLKS - WV_BLKS;
    }
    const int kb = HID / 32;
    const int k0 = (lb % kb) * 32;
    const int n0 = (lb / kb) * 32;
    const int x = tid & 31;
    const int y0 = tid >> 5;
#pragma unroll
    for (int y = y0; y < 32; y += 8)
        tile[y][x] = src[(size_t)(k0 + y) * N + n0 + x];
    __syncthreads();
#pragma unroll
    for (int y = y0; y < 32; y += 8)
        dst[(size_t)(n0 + y) * HID + k0 + x] = __float2half_rn(tile[x][y]);
}

// ======================= RoPE: 1 trig per (bs,i), applied to all heads ====
__global__ void rope_both(const float* __restrict__ Qf, const float* __restrict__ Kf,
                          const float* __restrict__ tvals, const float* __restrict__ rope_w,
                          __half* __restrict__ Qh, __half* __restrict__ Kh)
{
    const int idx = blockIdx.x * blockDim.x + threadIdx.x;
    if (idx >= MROWS * 64) return;
    const int i  = idx & 63;
    const int bs = idx >> 6;

    const float t = tvals[bs];
    const float inv_f = expf(-(float)(2 * i) * (9.210340371976184f / 128.0f));
    const float fr = t * inv_f * rope_w[i];
    const float cs = cosf(fr);
    const float sn = sinf(fr);

    const float* qrow = Qf + (size_t)bs * (NH * HD);
    __half* qo = Qh + (size_t)bs * (NH * HD);
#pragma unroll
    for (int h = 0; h < NH; h++) {
        const float x1 = qrow[h * HD + i];
        const float x2 = qrow[h * HD + i + 64];
        qo[h * HD + i]      = __float2half_rn(x1 * cs - x2 * sn);
        qo[h * HD + i + 64] = __float2half_rn(x2 * cs + x1 * sn);
    }
    const float* krow = Kf + (size_t)bs * (NKV * HD);
    __half* ko = Kh + (size_t)bs * (NKV * HD);
#pragma unroll
    for (int h = 0; h < NKV; h++) {
        const float x1 = krow[h * HD + i];
        const float x2 = krow[h * HD + i + 64];
        ko[h * HD + i]      = __float2half_rn(x1 * cs - x2 * sn);
        ko[h * HD + i + 64] = __float2half_rn(x2 * cs + x1 * sn);
    }
}

// ======================= GEMM common ======================================
#define GK   HID
#define CHK  32
#define NCHK (GK / CHK)        // 64
#define GPAD 40
#define GT_H (128 * GPAD)
#define NSTG 3
#define QSTG_B (2 * GT_H * 2)  // A + B per stage (20480 B)
#define GRID_PERS 444

// ---------- merged QKV GEMM: grid-stride over 24x32 tiles -----------------
#define QKV_TILES (24 * (MROWS/128))   // 768

__global__ __launch_bounds__(256) void qkv_gemm(
    const __half* __restrict__ Ah16,
    const __half* __restrict__ wq16, const __half* __restrict__ wk16,
    const __half* __restrict__ wv16,
    const float* __restrict__ bq, const float* __restrict__ bk,
    const float* __restrict__ bv,
    float* __restrict__ Qo, float* __restrict__ Ko, __half* __restrict__ Vo)
{
    extern __shared__ __half sg[];
    const uint32_t sbase = smem_u32(sg);

    const int tid  = threadIdx.x;
    const int lane = tid & 31;
    const int wid  = tid >> 5;
    const int wm   = wid & 3;
    const int wn   = wid >> 2;

    for (int tile = blockIdx.x; tile < QKV_TILES; tile += GRID_PERS) {
        const int nx = tile % 24;
        const int bm = (tile / 24) * 128;

        const __half* WT; const float* bias;
        float* outF = nullptr; __half* outH = nullptr;
        int N, bn;
        if (nx < 16)      { WT = wq16; bias = bq; outF = Qo; N = NH*HD;  bn = nx * 128; }
        else if (nx < 20) { WT = wk16; bias = bk; outF = Ko; N = NKV*HD; bn = (nx-16) * 128; }
        else              { WT = wv16; bias = bv; outH = Vo; N = NKV*HD; bn = (nx-20) * 128; }

        float c[2][8][4];
#pragma unroll
        for (int mi = 0; mi < 2; mi++)
#pragma unroll
            for (int ni = 0; ni < 8; ni++)
#pragma unroll
                for (int j = 0; j < 4; j++) c[mi][ni][j] = 0.f;

        auto issue = [&](int kt, int stg) {
            const uint32_t sb = sbase + stg * QSTG_B;
#pragma unroll
            for (int j = 0; j < 2; j++) {
                const int cch = tid * 2 + j;
                const int row = cch >> 2;
                const int off = (cch & 3) * 8;
                const uint32_t d = sb + (row * GPAD + off) * 2;
                cp16(d,            Ah16 + (size_t)(bm + row) * GK + kt * CHK + off);
                cp16(d + GT_H * 2, WT   + (size_t)(bn + row) * GK + kt * CHK + off);
            }
            CP_COMMIT();
        };

        issue(0, 0);
        issue(1, 1);

        for (int kt = 0; kt < NCHK; kt++) {
            CP_WAIT(1);
            __syncthreads();

            const uint32_t stage = sbase + (kt % NSTG) * QSTG_B;
            const uint32_t Ahs = stage;
            const uint32_t Bhs = Ahs + GT_H * 2;

#pragma unroll
            for (int ks = 0; ks < 2; ks++) {
                const int k0 = ks * 16;
                uint32_t ah[8];
#pragma unroll
                for (int mi = 0; mi < 2; mi++) {
                    const uint32_t aoff =
                        ((wm * 32 + mi * 16 + (lane & 7) + ((lane >> 3) & 1) * 8) * GPAD
                         + k0 + (lane >> 4) * 8) * 2;
                    ldsm4(ah + 4 * mi, Ahs + aoff);
                }
#pragma unroll
                for (int bg = 0; bg < 4; bg++) {
                    const uint32_t boff =
                        ((wn * 64 + bg * 16 + (lane & 7) + (lane >> 4) * 8) * GPAD
                         + k0 + ((lane >> 3) & 1) * 8) * 2;
                    uint32_t bh[4];
                    ldsm4(bh, Bhs + boff);
#pragma unroll
                    for (int tt = 0; tt < 2; tt++) {
                        const int ni = bg * 2 + tt;
                        mma_f16(c[0][ni], ah,     bh[2*tt], bh[2*tt+1]);
                        mma_f16(c[1][ni], ah + 4, bh[2*tt], bh[2*tt+1]);
                    }
                }
            }
            __syncthreads();
            if (kt + 2 < NCHK) issue(kt + 2, (kt + 2) % NSTG);
            else CP_COMMIT();
        }

#pragma unroll
        for (int mi = 0; mi < 2; mi++) {
            const int row0 = bm + wm * 32 + mi * 16 + (lane >> 2);
#pragma unroll
            for (int ni = 0; ni < 8; ni++) {
                const int col = bn + wn * 64 + ni * 8 + (lane & 3) * 2;
                const float b0 = __ldg(bias + col);
                const float b1 = __ldg(bias + col + 1);
                const float y00 = c[mi][ni][0] + b0, y01 = c[mi][ni][1] + b1;
                const float y10 = c[mi][ni][2] + b0, y11 = c[mi][ni][3] + b1;
                if (outH) {
                    *(uint32_t*)(outH + (size_t)row0 * N + col)       = packh2(y00, y01);
                    *(uint32_t*)(outH + (size_t)(row0 + 8) * N + col) = packh2(y10, y11);
                } else {
                    float2 r0, r1;
                    r0.x = y00; r0.y = y01;
                    r1.x = y10; r1.y = y11;
                    *(float2*)(outF + (size_t)row0 * N + col)       = r0;
                    *(float2*)(outF + (size_t)(row0 + 8) * N + col) = r1;
                }
            }
        }
    }
}

// ---------- WO GEMM: grid-stride over 16x32 tiles -------------------------
#define WO_TILES ((HID/128) * (MROWS/128))   // 512

__global__ __launch_bounds__(256) void wo_gemm(
    const __half* __restrict__ Agh, const __half* __restrict__ WTh,
    float* __restrict__ C, int N)
{
    extern __shared__ __half sg[];
    const uint32_t sbase = smem_u32(sg);

    const int tid  = threadIdx.x;
    const int lane = tid & 31;
    const int wid  = tid >> 5;
    const int wm   = wid & 3;
    const int wn   = wid >> 2;

    for (int tile = blockIdx.x; tile < WO_TILES; tile += GRID_PERS) {
        const int bn = (tile % (HID/128)) * 128;
        const int bm = (tile / (HID/128)) * 128;

        float c[2][8][4];
#pragma unroll
        for (int mi = 0; mi < 2; mi++)
#pragma unroll
            for (int ni = 0; ni < 8; ni++)
#pragma unroll
                for (int j = 0; j < 4; j++) c[mi][ni][j] = 0.f;

        auto issue = [&](int kt, int stg) {
            const uint32_t sb = sbase + stg * QSTG_B;
#pragma unroll
            for (int j = 0; j < 2; j++) {
                const int cch = tid * 2 + j;
                const int row = cch >> 2;
                const int off = (cch & 3) * 8;
                const uint32_t d = sb + (row * GPAD + off) * 2;
                cp16(d,            Agh + (size_t)(bm + row) * GK + kt * CHK + off);
                cp16(d + GT_H * 2, WTh + (size_t)(bn + row) * GK + kt * CHK + off);
            }
            CP_COMMIT();
        };

        issue(0, 0);
        issue(1, 1);

        for (int kt = 0; kt < NCHK; kt++) {
            CP_WAIT(1);
            __syncthreads();

            const uint32_t stage = sbase + (kt % NSTG) * QSTG_B;
            const uint32_t Ahs = stage;
            const uint32_t Bhs = Ahs + GT_H * 2;

#pragma unroll
            for (int ks = 0; ks < 2; ks++) {
                const int k0 = ks * 16;
                uint32_t ah[8];
#pragma unroll
                for (int mi = 0; mi < 2; mi++) {
                    const uint32_t aoff =
                        ((wm * 32 + mi * 16 + (lane & 7) + ((lane >> 3) & 1) * 8) * GPAD
                         + k0 + (lane >> 4) * 8) * 2;
                    ldsm4(ah + 4 * mi, Ahs + aoff);
                }
#pragma unroll
                for (int bg = 0; bg < 4; bg++) {
                    const uint32_t boff =
                        ((wn * 64 + bg * 16 + (lane & 7) + (lane >> 4) * 8) * GPAD
                         + k0 + ((lane >> 3) & 1) * 8) * 2;
                    uint32_t bh[4];
                    ldsm4(bh, Bhs + boff);
#pragma unroll
                    for (int tt = 0; tt < 2; tt++) {
                        const int ni = bg * 2 + tt;
                        mma_f16(c[0][ni], ah,     bh[2*tt], bh[2*tt+1]);
                        mma_f16(c[1][ni], ah + 4, bh[2*tt], bh[2*tt+1]);
                    }
                }
            }
            __syncthreads();
            if (kt + 2 < NCHK) issue(kt + 2, (kt + 2) % NSTG);
            else CP_COMMIT();
        }

#pragma unroll
        for (int mi = 0; mi < 2; mi++) {
            const int row0 = bm + wm * 32 + mi * 16 + (lane >> 2);
#pragma unroll
            for (int ni = 0; ni < 8; ni++) {
                const int col = bn + wn * 64 + ni * 8 + (lane & 3) * 2;
                float2 r0, r1;
                r0.x = c[mi][ni][0]; r0.y = c[mi][ni][1];
                r1.x = c[mi][ni][2]; r1.y = c[mi][ni][3];
                *(float2*)(C + (size_t)row0 * N + col)       = r0;
                *(float2*)(C + (size_t)(row0 + 8) * N + col) = r1;
            }
        }
    }
}

// ======================= Flash attention (R13 shape + Q-in-registers) =====
#define FPAD 136
#define FQT_H (128 * FPAD)
#define FKT_H (64 * FPAD)

__global__ __launch_bounds__(256) void flash_mma(
    const __half* __restrict__ Qg, const __half* __restrict__ Kg,
    const __half* __restrict__ Vg, __half* __restrict__ Oh)
{
    extern __shared__ __half sf[];
    const uint32_t uQ = smem_u32(sf);
    const uint32_t uK = uQ + FQT_H * 2;
    const uint32_t uV = uK + FKT_H * 2;

    const int qb = gridDim.x - 1 - blockIdx.x;   // heavy CTAs first
    const int bh = blockIdx.y;
    const int b  = bh >> 4;
    const int h  = bh & 15;
    const int kvh = h >> 2;
    const int tid = threadIdx.x;
    const int lane = tid & 31;
    const int w = tid >> 5;
    const int q0 = qb * 128;
    const int rowbase = b * S_LEN;

    // group 0: Q tile (128 rows x 128 halves)
    {
#pragma unroll
        for (int j = 0; j < 8; j++) {
            const int cch = tid * 8 + j;
            const int row = cch >> 4;
            const int off = (cch & 15) * 8;
            const size_t g = (size_t)(rowbase + q0 + row) * (NH * HD) + h * HD + off;
            cp16(uQ + (row * FPAD + off) * 2, Qg + g);
        }
        CP_COMMIT();
    }
    auto issueKV = [&](int nb) {
#pragma unroll
        for (int j = 0; j < 4; j++) {
            const int cch = tid * 4 + j;
            const int row = cch >> 4;
            const int off = (cch & 15) * 8;
            const size_t g = (size_t)(rowbase + nb * 64 + row) * (NKV * HD) + kvh * HD + off;
            const uint32_t d = (row * FPAD + off) * 2;
            cp16(uK + d, Kg + g);
            cp16(uV + d, Vg + g);
        }
        CP_COMMIT();
    };
    issueKV(0);     // group 1

    // wait for Q (group 0), leave KV0 in flight; hoist Q fragments to regs
    CP_WAIT(1);
    __syncthreads();
    uint32_t qf[8][4];
#pragma unroll
    for (int ks = 0; ks < 8; ks++) {
        const uint32_t aoff =
            ((w * 16 + (lane & 7) + ((lane >> 3) & 1) * 8) * FPAD
             + ks * 16 + (lane >> 4) * 8) * 2;
        ldsm4(qf[ks], uQ + aoff);
    }

    float o[16][4];
#pragma unroll
    for (int ni = 0; ni < 16; ni++)
#pragma unroll
        for (int j = 0; j < 4; j++) o[ni][j] = 0.f;
    float m0 = -1.0e30f, m1 = -1.0e30f, l0 = 0.f, l1 = 0.f;

    const float SC2 = 0.12751744900459843f;  // (1/sqrt(128)) * log2(e)
    const int nblocks = 2 * qb + 2;
    const int wrow0 = q0 + w * 16;

    for (int nb = 0; nb < nblocks; nb++) {
        const int n0 = nb * 64;
        CP_WAIT(0);
        __syncthreads();

        if (n0 <= wrow0 + 15) {
            float s[8][4];
#pragma unroll
            for (int ni = 0; ni < 8; ni++)
#pragma unroll
                for (int j = 0; j < 4; j++) s[ni][j] = 0.f;

#pragma unroll
            for (int ks = 0; ks < 8; ks++) {
                const int k0 = ks * 16;
#pragma unroll
                for (int bg = 0; bg < 4; bg++) {
                    const uint32_t boff =
                        ((bg * 16 + (lane & 7) + (lane >> 4) * 8) * FPAD
                         + k0 + ((lane >> 3) & 1) * 8) * 2;
                    uint32_t b4[4];
                    ldsm4(b4, uK + boff);
                    mma_f16(s[bg * 2],     qf[ks], b4[0], b4[1]);
                    mma_f16(s[bg * 2 + 1], qf[ks], b4[2], b4[3]);
                }
            }

            const int r0g = wrow0 + (lane >> 2);
            const int r1g = r0g + 8;
            const bool diag = (n0 + 63 > wrow0);
            float rmax0 = -1.0e30f, rmax1 = -1.0e30f;
#pragma unroll
            for (int ni = 0; ni < 8; ni++) {
                const int colb = n0 + ni * 8 + (lane & 3) * 2;
#pragma unroll
                for (int j = 0; j < 4; j++) {
                    float z = s[ni][j] * SC2;
                    if (diag) {
                        const int col = colb + (j & 1);
                        const int rw  = (j < 2) ? r0g : r1g;
                        if (col > rw) z = -1.0e30f;
                    }
                    s[ni][j] = z;
                }
                rmax0 = fmaxf(rmax0, fmaxf(s[ni][0], s[ni][1]));
                rmax1 = fmaxf(rmax1, fmaxf(s[ni][2], s[ni][3]));
            }
            rmax0 = fmaxf(rmax0, __shfl_xor_sync(0xffffffffu, rmax0, 1));
            rmax0 = fmaxf(rmax0, __shfl_xor_sync(0xffffffffu, rmax0, 2));
            rmax1 = fmaxf(rmax1, __shfl_xor_sync(0xffffffffu, rmax1, 1));
            rmax1 = fmaxf(rmax1, __shfl_xor_sync(0xffffffffu, rmax1, 2));

            const float mn0 = fmaxf(m0, rmax0);
            const float mn1 = fmaxf(m1, rmax1);
            const float al0 = ex2f(m0 - mn0);
            const float al1 = ex2f(m1 - mn1);
            m0 = mn0; m1 = mn1;

            float ls0 = 0.f, ls1 = 0.f;
#pragma unroll
            for (int ni = 0; ni < 8; ni++) {
                s[ni][0] = ex2f(s[ni][0] - mn0);
                s[ni][1] = ex2f(s[ni][1] - mn0);
                s[ni][2] = ex2f(s[ni][2] - mn1);
                s[ni][3] = ex2f(s[ni][3] - mn1);
                ls0 += s[ni][0] + s[ni][1];
                ls1 += s[ni][2] + s[ni][3];
            }
            l0 = l0 * al0 + ls0;
            l1 = l1 * al1 + ls1;
#pragma unroll
            for (int ni = 0; ni < 16; ni++) {
                o[ni][0] *= al0; o[ni][1] *= al0;
                o[ni][2] *= al1; o[ni][3] *= al1;
            }

#pragma unroll
            for (int kk = 0; kk < 4; kk++) {
                uint32_t ph[4];
                ph[0] = packh2(s[2*kk][0],   s[2*kk][1]);
                ph[1] = packh2(s[2*kk][2],   s[2*kk][3]);
                ph[2] = packh2(s[2*kk+1][0], s[2*kk+1][1]);
                ph[3] = packh2(s[2*kk+1][2], s[2*kk+1][3]);
#pragma unroll
                for (int vg = 0; vg < 8; vg++) {
                    const uint32_t voff =
                        ((kk * 16 + (lane & 7) + ((lane >> 3) & 1) * 8) * FPAD
                         + vg * 16 + (lane >> 4) * 8) * 2;
                    uint32_t v4[4];
                    ldsm4t(v4, uV + voff);
                    mma_f16(o[vg * 2],     ph, v4[0], v4[1]);
                    mma_f16(o[vg * 2 + 1], ph, v4[2], v4[3]);
                }
            }
        }

        __syncthreads();
        if (nb + 1 < nblocks) issueKV(nb + 1);
    }

    float lf0 = l0, lf1 = l1;
    lf0 += __shfl_xor_sync(0xffffffffu, lf0, 1);
    lf0 += __shfl_xor_sync(0xffffffffu, lf0, 2);
    lf1 += __shfl_xor_sync(0xffffffffu, lf1, 1);
    lf1 += __shfl_xor_sync(0xffffffffu, lf1, 2);
    const float inv0 = 1.f / lf0;
    const float inv1 = 1.f / lf1;

    const int gr0 = rowbase + wrow0 + (lane >> 2);
    const int gr1 = gr0 + 8;
#pragma unroll
    for (int ni = 0; ni < 16; ni++) {
        const int col = h * HD + ni * 8 + (lane & 3) * 2;
        *(uint32_t*)(Oh + (size_t)gr0 * (NH * HD) + col) =
            packh2(o[ni][0] * inv0, o[ni][1] * inv0);
        *(uint32_t*)(Oh + (size_t)gr1 * (NH * HD) + col) =
            packh2(o[ni][2] * inv1, o[ni][3] * inv1);
    }
}

// ======================= launch ===========================================
extern "C" void kernel_launch(void* const* d_in, const int* in_sizes, int n_in,
                              void* d_out, int out_size)
{
    const float* hidden = (const float*)d_in[0];
    const float* tvals  = (const float*)d_in[1];
    const float* wq     = (const float*)d_in[2];
    const float* bq     = (const float*)d_in[3];
    const float* wk     = (const float*)d_in[4];
    const float* bk     = (const float*)d_in[5];
    const float* wv     = (const float*)d_in[6];
    const float* bv     = (const float*)d_in[7];
    const float* wo     = (const float*)d_in[8];
    const float* rope_w = (const float*)d_in[9];
    float* out = (float*)d_out;

    float *q, *k;
    __half *hh, *qh, *kh, *vh, *oh, *wqh, *wkh, *wvh, *woh;
    cudaGetSymbolAddress((void**)&q,   g_q);
    cudaGetSymbolAddress((void**)&k,   g_k);
    cudaGetSymbolAddress((void**)&hh,  g_hh);
    cudaGetSymbolAddress((void**)&qh,  g_qh);
    cudaGetSymbolAddress((void**)&kh,  g_kh);
    cudaGetSymbolAddress((void**)&vh,  g_vh);
    cudaGetSymbolAddress((void**)&oh,  g_oh);
    cudaGetSymbolAddress((void**)&wqh, g_wqh);
    cudaGetSymbolAddress((void**)&wkh, g_wkh);
    cudaGetSymbolAddress((void**)&wvh, g_wvh);
    cudaGetSymbolAddress((void**)&woh, g_woh);

    // ---- prep ----
    prep_all<<<PREP_BLKS, 256>>>(wq, wk, wv, wo, hidden, wqh, wkh, wvh, woh, hh);

    // ---- merged QKV projection (grid-stride persistent) ----
    {
        const int qdyn = NSTG * QSTG_B;  // 61440
        cudaFuncSetAttribute(qkv_gemm, cudaFuncAttributeMaxDynamicSharedMemorySize, qdyn);
        qkv_gemm<<<GRID_PERS, 256, qdyn>>>(
            hh, wqh, wkh, wvh, bq, bk, bv, q, k, vh);
    }

    // ---- RoPE ----
    {
        int tot = MROWS * 64;
        rope_both<<<(tot + 255) / 256, 256>>>(q, k, tvals, rope_w, qh, kh);
    }

    // ---- Flash attention (R13 shape, Q fragments in registers) ----
    {
        const int fdyn = (FQT_H + 2 * FKT_H) * 2;  // 69632 B
        cudaFuncSetAttribute(flash_mma, cudaFuncAttributeMaxDynamicSharedMemorySize, fdyn);
        flash_mma<<<dim3(S_LEN/128, BATCH*NH), 256, fdyn>>>(qh, kh, vh, oh);
    }

    // ---- Output projection (grid-stride persistent) ----
    {
        const int wdyn = NSTG * QSTG_B;
        cudaFuncSetAttribute(wo_gemm, cudaFuncAttributeMaxDynamicSharedMemorySize, wdyn);
        wo_gemm<<<GRID_PERS, 256, wdyn>>>(oh, woh, out, HID);
    }
}